// round 12
// baseline (speedup 1.0000x reference)
#include <cuda_runtime.h>
#include <cstdint>
#include <math.h>

// ---------------- problem constants ----------------
constexpr int B        = 16384;
constexpr int NM       = 64;
constexpr int IN_F     = 6;
constexpr int OUT_F    = 3;
constexpr int HID      = 128;
constexpr int NFACT    = 4;

constexpr int MT       = 128;   // elements per tile (MMA M)
constexpr int XP       = 132;   // smem pitch (floats)
constexpr int NTHREADS = 256;   // 8 warps = 4 m-pairs x 2 n-halves
constexpr int NT_X     = 2;

constexpr int OFF_IDX  = B * NFACT * OUT_F;
constexpr int OFF_LOG  = OFF_IDX + B;
constexpr int OFF_PROB = OFF_LOG + B * NM;

#define DINL __device__ __forceinline__

// ---------------- device scratch ----------------
__device__ int g_idx[B];
__device__ int g_pcounts[64][NM];
__device__ int g_offsets[NM + 1];
__device__ int g_order[B];

// ---------------- kernel 1: select + histogram + easy outputs ----------------
__global__ void k_select(const float* __restrict__ inp, float* __restrict__ out) {
    __shared__ int h[NM];
    if (threadIdx.x < NM) h[threadIdx.x] = 0;
    __syncthreads();

    int b = blockIdx.x * blockDim.x + threadIdx.x;   // 64 blocks x 256
    float x0 = inp[b * 6 + 0];
    float x2 = inp[b * 6 + 2];
    const float TPf = 6.2831853071795864769f;
    float ang = (float)atan2((double)x2, (double)x0); // correctly-rounded f32 atan2
    float t   = ang + TPf;
    float a   = fmodf(t, TPf);
    float v   = a / TPf * 64.0f;
    int idx = (int)floorf(v);
    idx = max(0, min(63, idx));

    g_idx[b] = idx;
    out[OFF_IDX + b] = (float)idx;
    atomicAdd(&h[idx], 1);

    // logits=1, probs=1/64 — fully coalesced grid-linear float4 writes
    float4 ones = make_float4(1.f, 1.f, 1.f, 1.f);
    float4 prob = make_float4(0.015625f, 0.015625f, 0.015625f, 0.015625f);
    float4* lg = (float4*)(out + OFF_LOG);
    float4* pb = (float4*)(out + OFF_PROB);
    size_t base = (size_t)blockIdx.x * (256 * 16) + threadIdx.x;
    #pragma unroll
    for (int i = 0; i < 16; ++i) {
        lg[base + (size_t)i * 256] = ones;
        pb[base + (size_t)i * 256] = prob;
    }

    __syncthreads();
    if (threadIdx.x < NM) g_pcounts[blockIdx.x][threadIdx.x] = h[threadIdx.x];
}

// ---------------- kernel 2: local scan + scatter (no global atomics) --------
__global__ void k_scatter() {
    __shared__ int cur[NM];
    __shared__ int ws[2];
    int tid = threadIdx.x;

    int tot = 0, pre = 0, v = 0;
    if (tid < NM) {
        #pragma unroll 8
        for (int j = 0; j < 64; ++j) {
            int c = g_pcounts[j][tid];
            if (j < (int)blockIdx.x) pre += c;
            tot += c;
        }
        v = tot;
        #pragma unroll
        for (int d = 1; d < 32; d <<= 1) {
            int n = __shfl_up_sync(0xFFFFFFFFu, v, d);
            if ((tid & 31) >= d) v += n;
        }
        if ((tid & 31) == 31) ws[tid >> 5] = v;
    }
    __syncthreads();
    if (tid >= 32 && tid < NM) v += ws[0];
    if (tid < NM) {
        cur[tid] = (v - tot) + pre;
        if (blockIdx.x == 0) {
            g_offsets[tid + 1] = v;
            if (tid == 0) g_offsets[0] = 0;
        }
    }
    __syncthreads();

    int b = blockIdx.x * blockDim.x + tid;
    int idx = g_idx[b];
    int pos = atomicAdd(&cur[idx], 1);
    g_order[pos] = b;
}

// ---------------- tf32 / mma helpers ----------------
DINL uint32_t tf32u(float x) {
    uint32_t r;
    asm("cvt.rna.tf32.f32 %0, %1;" : "=r"(r) : "f"(x));
    return r;
}
DINL float tf32f(float x) { return __uint_as_float(tf32u(x)); }

DINL void mma8(float& c0, float& c1, float& c2, float& c3,
               uint32_t a0, uint32_t a1, uint32_t a2, uint32_t a3,
               uint32_t b0, uint32_t b1) {
    asm volatile(
        "mma.sync.aligned.m16n8k8.row.col.f32.tf32.tf32.f32 "
        "{%0,%1,%2,%3}, {%4,%5,%6,%7}, {%8,%9}, {%0,%1,%2,%3};"
        : "+f"(c0), "+f"(c1), "+f"(c2), "+f"(c3)
        : "r"(a0), "r"(a1), "r"(a2), "r"(a3), "r"(b0), "r"(b1));
}

DINL uint32_t smem_u32(const void* p) {
    uint32_t a;
    asm("{ .reg .u64 t; cvta.to.shared.u64 t, %1; cvt.u32.u64 %0, t; }" : "=r"(a) : "l"(p));
    return a;
}
DINL void cpa16(uint32_t dst, const float* src) {
    asm volatile("cp.async.cg.shared.global [%0], [%1], 16;" :: "r"(dst), "l"(src));
}
#define CP_COMMIT() asm volatile("cp.async.commit_group;" ::: "memory")
#define CP_WAIT0()  asm volatile("cp.async.wait_group 0;" ::: "memory")

// ---------------- async staging (raw fp32, row-major [n][k], pitch XP) ------
template<int H>
DINL void stage_wh_async(const float* __restrict__ Wg, uint32_t dst_u) {
    constexpr int J = H / 4;
    for (int i = threadIdx.x; i < H * J; i += NTHREADS) {
        int n = i / J, j = i - n * J;
        cpa16(dst_u + (uint32_t)(n * XP + 4 * j) * 4, Wg + n * HID + 4 * j);
    }
}
template<int H>
DINL void stage_w4_async(const float* __restrict__ Wg, uint32_t dst_u) {
    constexpr int J = H / 4;
    for (int i = threadIdx.x; i < OUT_F * J; i += NTHREADS) {
        int o = i / J, j = i - o * J;
        cpa16(dst_u + (uint32_t)(o * XP + 4 * j) * 4, Wg + o * HID + 4 * j);
    }
}
template<int H>
DINL void stage_b_async(const float* __restrict__ bg, uint32_t dst_u) {
    if (threadIdx.x < H / 4) cpa16(dst_u + threadIdx.x * 16, bg + 4 * threadIdx.x);
}
template<int H>
DINL void stage_w0(const float* __restrict__ Wg, float* __restrict__ Ws) {
    for (int n = threadIdx.x; n < H; n += NTHREADS) {
        const float* src = Wg + n * IN_F;
        float* dst = Ws + n * XP;
        dst[0] = src[0]; dst[1] = src[1]; dst[2] = src[2];
        dst[3] = src[3]; dst[4] = src[4]; dst[5] = src[5];
        dst[6] = 0.f; dst[7] = 0.f;
    }
}

// ---------------- fused FC layer: M-block2 x N-half, in-place X -------------
// Warp (mpair, nhalf): rows [mpair*32, +32) as two 16-row m-tiles,
// n-chunks [nhalf*8, +8). Each B fragment feeds 2 mma (both m-tiles).
// In-place safety: ALL warps preload their A fragments, then one
// __syncthreads, then compute+store (two warps share rows -> cross-warp).
template<int KC>
DINL void layer_fc(float* __restrict__ X, const float* __restrict__ Ws,
                   const float* __restrict__ Bs,
                   int mpair, int nhalf, int g, int tig) {
    const int r0 = mpair * 32;
    uint32_t a[2][KC][4];
    #pragma unroll
    for (int mt = 0; mt < 2; ++mt) {
        #pragma unroll
        for (int kc = 0; kc < KC; ++kc) {
            const float* xr = X + (r0 + mt * 16 + g) * XP + kc * 8 + tig;
            a[mt][kc][0] = __float_as_uint(xr[0]);
            a[mt][kc][2] = __float_as_uint(xr[4]);
            a[mt][kc][1] = __float_as_uint(xr[8 * XP]);
            a[mt][kc][3] = __float_as_uint(xr[8 * XP + 4]);
        }
    }
    __syncthreads();

    #pragma unroll
    for (int ncg = 0; ncg < 2; ++ncg) {
        const int ncb = nhalf * 8 + ncg * 4;
        float c[2][4][4];
        #pragma unroll
        for (int q = 0; q < 4; ++q) {
            float2 bi = *(const float2*)(Bs + (ncb + q) * 8 + 2 * tig);
            #pragma unroll
            for (int mt = 0; mt < 2; ++mt) {
                c[mt][q][0] = bi.x; c[mt][q][1] = bi.y;
                c[mt][q][2] = bi.x; c[mt][q][3] = bi.y;
            }
        }
        #pragma unroll
        for (int kc = 0; kc < KC; ++kc) {
            #pragma unroll
            for (int q = 0; q < 4; ++q) {
                const float* w = Ws + ((ncb + q) * 8 + g) * XP + kc * 8 + tig;
                uint32_t b0 = __float_as_uint(w[0]);
                uint32_t b1 = __float_as_uint(w[4]);
                mma8(c[0][q][0], c[0][q][1], c[0][q][2], c[0][q][3],
                     a[0][kc][0], a[0][kc][1], a[0][kc][2], a[0][kc][3], b0, b1);
                mma8(c[1][q][0], c[1][q][1], c[1][q][2], c[1][q][3],
                     a[1][kc][0], a[1][kc][1], a[1][kc][2], a[1][kc][3], b0, b1);
            }
        }
        #pragma unroll
        for (int mt = 0; mt < 2; ++mt) {
            #pragma unroll
            for (int q = 0; q < 4; ++q) {
                const int n0 = (ncb + q) * 8;
                float2 v;
                v.x = tf32f(fmaxf(c[mt][q][0], 0.f));
                v.y = tf32f(fmaxf(c[mt][q][1], 0.f));
                *(float2*)(X + (r0 + mt * 16 + g) * XP + n0 + 2 * tig) = v;
                v.x = tf32f(fmaxf(c[mt][q][2], 0.f));
                v.y = tf32f(fmaxf(c[mt][q][3], 0.f));
                *(float2*)(X + (r0 + mt * 16 + 8 + g) * XP + n0 + 2 * tig) = v;
            }
        }
    }
}

// output layer: 8 warps x 16 rows (classic split), N=8 (3 valid), no X writes
template<int KC>
DINL void layer_out(const float* __restrict__ X, const float* __restrict__ Ws,
                    const float* __restrict__ Bs, float* __restrict__ out,
                    const int* __restrict__ ords, int cnt, int fi,
                    int e0, int g, int tig) {
    uint32_t a[KC][4];
    #pragma unroll
    for (int kc = 0; kc < KC; ++kc) {
        const float* xr = X + (e0 + g) * XP + kc * 8 + tig;
        a[kc][0] = __float_as_uint(xr[0]);
        a[kc][2] = __float_as_uint(xr[4]);
        a[kc][1] = __float_as_uint(xr[8 * XP]);
        a[kc][3] = __float_as_uint(xr[8 * XP + 4]);
    }
    float c0 = Bs[2 * tig], c1 = Bs[2 * tig + 1];
    float c2 = c0, c3 = c1;
    #pragma unroll
    for (int kc = 0; kc < KC; ++kc) {
        const float* w = Ws + g * XP + kc * 8 + tig;
        mma8(c0, c1, c2, c3, a[kc][0], a[kc][1], a[kc][2], a[kc][3],
             __float_as_uint(w[0]), __float_as_uint(w[4]));
    }
    const int col0 = 2 * tig, col1 = 2 * tig + 1;
    const int e1 = e0 + g, e2 = e0 + 8 + g;
    if (e1 < cnt) {
        const int base = ords[e1] * (NFACT * OUT_F) + fi * OUT_F;
        if (col0 < OUT_F) out[base + col0] = c0;
        if (col1 < OUT_F) out[base + col1] = c1;
    }
    if (e2 < cnt) {
        const int base = ords[e2] * (NFACT * OUT_F) + fi * OUT_F;
        if (col0 < OUT_F) out[base + col0] = c2;
        if (col1 < OUT_F) out[base + col1] = c3;
    }
}

// ---------------- fused MLP kernel ----------------
template<int H>
DINL void mlp_body(const float* __restrict__ inp,
                   const float* __restrict__ W0, const float* __restrict__ b0,
                   const float* __restrict__ W1, const float* __restrict__ b1,
                   const float* __restrict__ W2, const float* __restrict__ b2,
                   const float* __restrict__ W3, const float* __restrict__ b3,
                   const float* __restrict__ W4, const float* __restrict__ b4,
                   float* __restrict__ out) {
    extern __shared__ float sm[];
    float* X   = sm;                     // MT*XP
    float* wsA = X + MT * XP;            // HID*XP
    float* wsB = wsA + HID * XP;         // HID*XP
    float* bsA = wsB + HID * XP;         // HID
    float* bsB = bsA + HID;              // HID
    int*  ords = (int*)(bsB + HID);      // MT
    const uint32_t wsA_u = smem_u32(wsA);
    const uint32_t wsB_u = smem_u32(wsB);
    const uint32_t bsA_u = smem_u32(bsA);
    const uint32_t bsB_u = smem_u32(bsB);

    constexpr int KC = H / 8;
    constexpr int fi = H / 32 - 1;

    const int tid = threadIdx.x;
    const int wid = tid >> 5;
    const int lane = tid & 31;
    const int g = lane >> 2, tig = lane & 3;
    const int mpair = wid >> 1, nhalf = wid & 1;
    const int e0 = wid * 16;

    const int m = blockIdx.y;
    const int off0 = g_offsets[m];
    const int off1 = g_offsets[m + 1];

    const float* Wg0 = W0 + m * (HID * IN_F);
    const float* Wg1 = W1 + m * (HID * HID);
    const float* Wg2 = W2 + m * (HID * HID);
    const float* Wg3 = W3 + m * (HID * HID);
    const float* Wg4 = W4 + m * (OUT_F * HID);

    for (int tile = blockIdx.x; off0 + tile * MT < off1; tile += NT_X) {
        const int beg = off0 + tile * MT;
        const int cnt = min(MT, off1 - beg);

        for (int i = tid; i < MT; i += NTHREADS)
            ords[i] = (i < cnt) ? g_order[beg + i] : 0;
        __syncthreads();

        for (int i = tid; i < MT * 8; i += NTHREADS) {
            int e = i >> 3, c = i & 7;
            X[e * XP + c] = (c < IN_F) ? tf32f(inp[(size_t)ords[e] * IN_F + c]) : 0.f;
        }
        stage_w0<H>(Wg0, wsA);
        for (int i = tid; i < H; i += NTHREADS) bsA[i] = b0[m * HID + i];
        __syncthreads();

        // L0 (wsA); prefetch W1 -> wsB
        stage_wh_async<H>(Wg1, wsB_u);
        stage_b_async<H>(b1 + m * HID, bsB_u);
        CP_COMMIT();
        layer_fc<1>(X, wsA, bsA, mpair, nhalf, g, tig);
        CP_WAIT0(); __syncthreads();

        // L1 (wsB); prefetch W2 -> wsA
        stage_wh_async<H>(Wg2, wsA_u);
        stage_b_async<H>(b2 + m * HID, bsA_u);
        CP_COMMIT();
        layer_fc<KC>(X, wsB, bsB, mpair, nhalf, g, tig);
        CP_WAIT0(); __syncthreads();

        // L2 (wsA); prefetch W3 -> wsB
        stage_wh_async<H>(Wg3, wsB_u);
        stage_b_async<H>(b3 + m * HID, bsB_u);
        CP_COMMIT();
        layer_fc<KC>(X, wsA, bsA, mpair, nhalf, g, tig);
        CP_WAIT0(); __syncthreads();

        // L3 (wsB); prefetch W4 -> wsA + bias4 -> bsA
        stage_w4_async<H>(Wg4, wsA_u);
        if (tid < 8) bsA[tid] = (tid < OUT_F) ? b4[m * OUT_F + tid] : 0.f;
        CP_COMMIT();
        layer_fc<KC>(X, wsB, bsB, mpair, nhalf, g, tig);
        CP_WAIT0(); __syncthreads();

        // L4 out (wsA)
        layer_out<KC>(X, wsA, bsA, out, ords, cnt, fi, e0, g, tig);
        __syncthreads();
    }
}

__global__ __launch_bounds__(NTHREADS, 1) void k_mlp_all(
    const float* __restrict__ inp,
    const float* __restrict__ W0, const float* __restrict__ b0,
    const float* __restrict__ W1, const float* __restrict__ b1,
    const float* __restrict__ W2, const float* __restrict__ b2,
    const float* __restrict__ W3, const float* __restrict__ b3,
    const float* __restrict__ W4, const float* __restrict__ b4,
    float* __restrict__ out) {
    switch (blockIdx.z) {
        case 0: mlp_body<32 >(inp, W0, b0, W1, b1, W2, b2, W3, b3, W4, b4, out); break;
        case 1: mlp_body<64 >(inp, W0, b0, W1, b1, W2, b2, W3, b3, W4, b4, out); break;
        case 2: mlp_body<96 >(inp, W0, b0, W1, b1, W2, b2, W3, b3, W4, b4, out); break;
        default: mlp_body<128>(inp, W0, b0, W1, b1, W2, b2, W3, b3, W4, b4, out); break;
    }
}

// ---------------- launch ----------------
extern "C" void kernel_launch(void* const* d_in, const int* in_sizes, int n_in,
                              void* d_out, int out_size) {
    const float* inp = (const float*)d_in[0];
    const float* W0  = (const float*)d_in[1];
    const float* b0  = (const float*)d_in[2];
    const float* W1  = (const float*)d_in[3];
    const float* b1  = (const float*)d_in[4];
    const float* W2  = (const float*)d_in[5];
    const float* b2  = (const float*)d_in[6];
    const float* W3  = (const float*)d_in[7];
    const float* b3  = (const float*)d_in[8];
    const float* W4  = (const float*)d_in[9];
    const float* b4  = (const float*)d_in[10];
    float* out = (float*)d_out;

    k_select<<<B / 256, 256>>>(inp, out);
    k_scatter<<<B / 256, 256>>>();

    size_t smem = (size_t)(MT * XP + 2 * HID * XP + 2 * HID) * sizeof(float) + MT * sizeof(int);
    cudaFuncSetAttribute(k_mlp_all, cudaFuncAttributeMaxDynamicSharedMemorySize, (int)smem);
    dim3 grid(NT_X, NM, NFACT);
    k_mlp_all<<<grid, NTHREADS, smem>>>(inp, W0, b0, W1, b1, W2, b2, W3, b3, W4, b4, out);
}

// round 13
// speedup vs baseline: 1.2123x; 1.2123x over previous
#include <cuda_runtime.h>
#include <cstdint>
#include <math.h>

// ---------------- problem constants ----------------
constexpr int B        = 16384;
constexpr int NM       = 64;
constexpr int IN_F     = 6;
constexpr int OUT_F    = 3;
constexpr int HID      = 128;
constexpr int NFACT    = 4;

constexpr int MT       = 128;   // elements per tile (MMA M)
constexpr int XP       = 132;   // smem pitch (floats)
constexpr int NTHREADS = 256;   // 8 warps = 4 m-pairs x 2 n-halves
constexpr int NT_X     = 2;

constexpr int OFF_IDX  = B * NFACT * OUT_F;
constexpr int OFF_LOG  = OFF_IDX + B;
constexpr int OFF_PROB = OFF_LOG + B * NM;

#define DINL __device__ __forceinline__

// ---------------- device scratch ----------------
__device__ int g_idx[B];
__device__ int g_pcounts[64][NM];
__device__ int g_offsets[NM + 1];
__device__ int g_order[B];

// ---------------- kernel 1: select + histogram + easy outputs ----------------
__global__ void k_select(const float* __restrict__ inp, float* __restrict__ out) {
    __shared__ int h[NM];
    if (threadIdx.x < NM) h[threadIdx.x] = 0;
    __syncthreads();

    int b = blockIdx.x * blockDim.x + threadIdx.x;   // 64 blocks x 256
    float x0 = inp[b * 6 + 0];
    float x2 = inp[b * 6 + 2];
    const float TPf = 6.2831853071795864769f;
    float ang = (float)atan2((double)x2, (double)x0); // correctly-rounded f32 atan2
    float t   = ang + TPf;
    float a   = fmodf(t, TPf);
    float v   = a / TPf * 64.0f;
    int idx = (int)floorf(v);
    idx = max(0, min(63, idx));

    g_idx[b] = idx;
    out[OFF_IDX + b] = (float)idx;
    atomicAdd(&h[idx], 1);

    // logits=1, probs=1/64 — fully coalesced grid-linear float4 writes
    float4 ones = make_float4(1.f, 1.f, 1.f, 1.f);
    float4 prob = make_float4(0.015625f, 0.015625f, 0.015625f, 0.015625f);
    float4* lg = (float4*)(out + OFF_LOG);
    float4* pb = (float4*)(out + OFF_PROB);
    size_t base = (size_t)blockIdx.x * (256 * 16) + threadIdx.x;
    #pragma unroll
    for (int i = 0; i < 16; ++i) {
        lg[base + (size_t)i * 256] = ones;
        pb[base + (size_t)i * 256] = prob;
    }

    __syncthreads();
    if (threadIdx.x < NM) g_pcounts[blockIdx.x][threadIdx.x] = h[threadIdx.x];
}

// ---------------- kernel 2: local scan + scatter (no global atomics) --------
__global__ void k_scatter() {
    __shared__ int cur[NM];
    __shared__ int ws[2];
    int tid = threadIdx.x;

    int tot = 0, pre = 0, v = 0;
    if (tid < NM) {
        #pragma unroll 8
        for (int j = 0; j < 64; ++j) {
            int c = g_pcounts[j][tid];
            if (j < (int)blockIdx.x) pre += c;
            tot += c;
        }
        v = tot;
        #pragma unroll
        for (int d = 1; d < 32; d <<= 1) {
            int n = __shfl_up_sync(0xFFFFFFFFu, v, d);
            if ((tid & 31) >= d) v += n;
        }
        if ((tid & 31) == 31) ws[tid >> 5] = v;
    }
    __syncthreads();
    if (tid >= 32 && tid < NM) v += ws[0];
    if (tid < NM) {
        cur[tid] = (v - tot) + pre;
        if (blockIdx.x == 0) {
            g_offsets[tid + 1] = v;
            if (tid == 0) g_offsets[0] = 0;
        }
    }
    __syncthreads();

    int b = blockIdx.x * blockDim.x + tid;
    int idx = g_idx[b];
    int pos = atomicAdd(&cur[idx], 1);
    g_order[pos] = b;
}

// ---------------- tf32 / mma helpers ----------------
DINL uint32_t tf32u(float x) {
    uint32_t r;
    asm("cvt.rna.tf32.f32 %0, %1;" : "=r"(r) : "f"(x));
    return r;
}
DINL float tf32f(float x) { return __uint_as_float(tf32u(x)); }

DINL void mma8(float& c0, float& c1, float& c2, float& c3,
               uint32_t a0, uint32_t a1, uint32_t a2, uint32_t a3,
               uint32_t b0, uint32_t b1) {
    asm volatile(
        "mma.sync.aligned.m16n8k8.row.col.f32.tf32.tf32.f32 "
        "{%0,%1,%2,%3}, {%4,%5,%6,%7}, {%8,%9}, {%0,%1,%2,%3};"
        : "+f"(c0), "+f"(c1), "+f"(c2), "+f"(c3)
        : "r"(a0), "r"(a1), "r"(a2), "r"(a3), "r"(b0), "r"(b1));
}

DINL uint32_t smem_u32(const void* p) {
    uint32_t a;
    asm("{ .reg .u64 t; cvta.to.shared.u64 t, %1; cvt.u32.u64 %0, t; }" : "=r"(a) : "l"(p));
    return a;
}
DINL void cpa16(uint32_t dst, const float* src) {
    asm volatile("cp.async.cg.shared.global [%0], [%1], 16;" :: "r"(dst), "l"(src));
}
#define CP_COMMIT() asm volatile("cp.async.commit_group;" ::: "memory")
#define CP_WAIT0()  asm volatile("cp.async.wait_group 0;" ::: "memory")
#define BAR_PAIR(id) asm volatile("bar.sync %0, 64;" :: "r"(id) : "memory")

// ---------------- async staging (raw fp32, row-major [n][k], pitch XP) ------
template<int H>
DINL void stage_wh_async(const float* __restrict__ Wg, uint32_t dst_u) {
    constexpr int J = H / 4;
    for (int i = threadIdx.x; i < H * J; i += NTHREADS) {
        int n = i / J, j = i - n * J;
        cpa16(dst_u + (uint32_t)(n * XP + 4 * j) * 4, Wg + n * HID + 4 * j);
    }
}
template<int H>
DINL void stage_w4_async(const float* __restrict__ Wg, uint32_t dst_u) {
    constexpr int J = H / 4;
    for (int i = threadIdx.x; i < OUT_F * J; i += NTHREADS) {
        int o = i / J, j = i - o * J;
        cpa16(dst_u + (uint32_t)(o * XP + 4 * j) * 4, Wg + o * HID + 4 * j);
    }
}
template<int H>
DINL void stage_b_async(const float* __restrict__ bg, uint32_t dst_u) {
    if (threadIdx.x < H / 4) cpa16(dst_u + threadIdx.x * 16, bg + 4 * threadIdx.x);
}
template<int H>
DINL void stage_w0(const float* __restrict__ Wg, float* __restrict__ Ws) {
    for (int n = threadIdx.x; n < H; n += NTHREADS) {
        const float* src = Wg + n * IN_F;
        float* dst = Ws + n * XP;
        dst[0] = src[0]; dst[1] = src[1]; dst[2] = src[2];
        dst[3] = src[3]; dst[4] = src[4]; dst[5] = src[5];
        dst[6] = 0.f; dst[7] = 0.f;
    }
}

// ---------------- fused FC layer v2: M-block2, two-phase K, pair barriers ---
// Warp (mpair, nhalf): rows [mpair*32,+32) (two m-tiles), n-chunks
// [nhalf*NCW, +NCW). Each B fragment feeds 2 mma. A fragments held for
// KC/2 chunks at a time (bounded regs); accumulators live across phases.
// In-place X safety: only the pair (2*mpair, 2*mpair+1) shares rows ->
// named barrier (64 threads) between last A-read and first store.
// Per-neuron accumulation order: bias + k ascending (identical to prior).
template<int KC, int NCW>
DINL void layer_fc(float* __restrict__ X, const float* __restrict__ Ws,
                   const float* __restrict__ Bs,
                   int mpair, int nhalf, int g, int tig) {
    const int r0 = mpair * 32;
    constexpr int NPH = (KC > 1) ? 2 : 1;
    constexpr int KH  = KC / NPH;

    float c[2][NCW][4];
    #pragma unroll
    for (int nc = 0; nc < NCW; ++nc) {
        float2 bi = *(const float2*)(Bs + (nhalf * NCW + nc) * 8 + 2 * tig);
        #pragma unroll
        for (int mt = 0; mt < 2; ++mt) {
            c[mt][nc][0] = bi.x; c[mt][nc][1] = bi.y;
            c[mt][nc][2] = bi.x; c[mt][nc][3] = bi.y;
        }
    }

    #pragma unroll
    for (int ph = 0; ph < NPH; ++ph) {
        uint32_t a[2][KH][4];
        #pragma unroll
        for (int mt = 0; mt < 2; ++mt) {
            #pragma unroll
            for (int j = 0; j < KH; ++j) {
                const float* xr = X + (r0 + mt * 16 + g) * XP + (ph * KH + j) * 8 + tig;
                a[mt][j][0] = __float_as_uint(xr[0]);
                a[mt][j][2] = __float_as_uint(xr[4]);
                a[mt][j][1] = __float_as_uint(xr[8 * XP]);
                a[mt][j][3] = __float_as_uint(xr[8 * XP + 4]);
            }
        }
        #pragma unroll
        for (int nc = 0; nc < NCW; ++nc) {
            const int row = (nhalf * NCW + nc) * 8 + g;
            #pragma unroll
            for (int j = 0; j < KH; ++j) {
                const float* w = Ws + row * XP + (ph * KH + j) * 8 + tig;
                uint32_t b0 = __float_as_uint(w[0]);
                uint32_t b1 = __float_as_uint(w[4]);
                mma8(c[0][nc][0], c[0][nc][1], c[0][nc][2], c[0][nc][3],
                     a[0][j][0], a[0][j][1], a[0][j][2], a[0][j][3], b0, b1);
                mma8(c[1][nc][0], c[1][nc][1], c[1][nc][2], c[1][nc][3],
                     a[1][j][0], a[1][j][1], a[1][j][2], a[1][j][3], b0, b1);
            }
        }
    }

    BAR_PAIR(1 + mpair);   // pair-local: A reads done before partner stores

    #pragma unroll
    for (int mt = 0; mt < 2; ++mt) {
        #pragma unroll
        for (int nc = 0; nc < NCW; ++nc) {
            const int n0 = (nhalf * NCW + nc) * 8;
            float2 v;
            v.x = tf32f(fmaxf(c[mt][nc][0], 0.f));
            v.y = tf32f(fmaxf(c[mt][nc][1], 0.f));
            *(float2*)(X + (r0 + mt * 16 + g) * XP + n0 + 2 * tig) = v;
            v.x = tf32f(fmaxf(c[mt][nc][2], 0.f));
            v.y = tf32f(fmaxf(c[mt][nc][3], 0.f));
            *(float2*)(X + (r0 + mt * 16 + 8 + g) * XP + n0 + 2 * tig) = v;
        }
    }
}

// output layer: 8 warps x 16 rows, N=8 (3 valid), no X writes
template<int KC>
DINL void layer_out(const float* __restrict__ X, const float* __restrict__ Ws,
                    const float* __restrict__ Bs, float* __restrict__ out,
                    const int* __restrict__ ords, int cnt, int fi,
                    int e0, int g, int tig) {
    uint32_t a[KC][4];
    #pragma unroll
    for (int kc = 0; kc < KC; ++kc) {
        const float* xr = X + (e0 + g) * XP + kc * 8 + tig;
        a[kc][0] = __float_as_uint(xr[0]);
        a[kc][2] = __float_as_uint(xr[4]);
        a[kc][1] = __float_as_uint(xr[8 * XP]);
        a[kc][3] = __float_as_uint(xr[8 * XP + 4]);
    }
    float c0 = Bs[2 * tig], c1 = Bs[2 * tig + 1];
    float c2 = c0, c3 = c1;
    #pragma unroll
    for (int kc = 0; kc < KC; ++kc) {
        const float* w = Ws + g * XP + kc * 8 + tig;
        mma8(c0, c1, c2, c3, a[kc][0], a[kc][1], a[kc][2], a[kc][3],
             __float_as_uint(w[0]), __float_as_uint(w[4]));
    }
    const int col0 = 2 * tig, col1 = 2 * tig + 1;
    const int e1 = e0 + g, e2 = e0 + 8 + g;
    if (e1 < cnt) {
        const int base = ords[e1] * (NFACT * OUT_F) + fi * OUT_F;
        if (col0 < OUT_F) out[base + col0] = c0;
        if (col1 < OUT_F) out[base + col1] = c1;
    }
    if (e2 < cnt) {
        const int base = ords[e2] * (NFACT * OUT_F) + fi * OUT_F;
        if (col0 < OUT_F) out[base + col0] = c2;
        if (col1 < OUT_F) out[base + col1] = c3;
    }
}

// ---------------- fused MLP kernel ----------------
template<int H>
DINL void mlp_body(const float* __restrict__ inp,
                   const float* __restrict__ W0, const float* __restrict__ b0,
                   const float* __restrict__ W1, const float* __restrict__ b1,
                   const float* __restrict__ W2, const float* __restrict__ b2,
                   const float* __restrict__ W3, const float* __restrict__ b3,
                   const float* __restrict__ W4, const float* __restrict__ b4,
                   float* __restrict__ out) {
    extern __shared__ float sm[];
    float* X   = sm;                     // MT*XP
    float* wsA = X + MT * XP;            // HID*XP
    float* wsB = wsA + HID * XP;         // HID*XP
    float* bsA = wsB + HID * XP;         // HID
    float* bsB = bsA + HID;              // HID
    int*  ords = (int*)(bsB + HID);      // MT
    const uint32_t wsA_u = smem_u32(wsA);
    const uint32_t wsB_u = smem_u32(wsB);
    const uint32_t bsA_u = smem_u32(bsA);
    const uint32_t bsB_u = smem_u32(bsB);

    constexpr int KC  = H / 8;
    constexpr int NCW = H / 16;
    constexpr int fi  = H / 32 - 1;

    const int tid = threadIdx.x;
    const int wid = tid >> 5;
    const int lane = tid & 31;
    const int g = lane >> 2, tig = lane & 3;
    const int mpair = wid >> 1, nhalf = wid & 1;
    const int e0 = wid * 16;

    const int m = blockIdx.y;
    const int off0 = g_offsets[m];
    const int off1 = g_offsets[m + 1];

    const float* Wg0 = W0 + m * (HID * IN_F);
    const float* Wg1 = W1 + m * (HID * HID);
    const float* Wg2 = W2 + m * (HID * HID);
    const float* Wg3 = W3 + m * (HID * HID);
    const float* Wg4 = W4 + m * (OUT_F * HID);

    for (int tile = blockIdx.x; off0 + tile * MT < off1; tile += NT_X) {
        const int beg = off0 + tile * MT;
        const int cnt = min(MT, off1 - beg);

        for (int i = tid; i < MT; i += NTHREADS)
            ords[i] = (i < cnt) ? g_order[beg + i] : 0;
        __syncthreads();

        for (int i = tid; i < MT * 8; i += NTHREADS) {
            int e = i >> 3, c = i & 7;
            X[e * XP + c] = (c < IN_F) ? tf32f(inp[(size_t)ords[e] * IN_F + c]) : 0.f;
        }
        stage_w0<H>(Wg0, wsA);
        for (int i = tid; i < H; i += NTHREADS) bsA[i] = b0[m * HID + i];
        __syncthreads();

        // L0 (wsA); prefetch W1 -> wsB
        stage_wh_async<H>(Wg1, wsB_u);
        stage_b_async<H>(b1 + m * HID, bsB_u);
        CP_COMMIT();
        layer_fc<1, NCW>(X, wsA, bsA, mpair, nhalf, g, tig);
        CP_WAIT0(); __syncthreads();

        // L1 (wsB); prefetch W2 -> wsA
        stage_wh_async<H>(Wg2, wsA_u);
        stage_b_async<H>(b2 + m * HID, bsA_u);
        CP_COMMIT();
        layer_fc<KC, NCW>(X, wsB, bsB, mpair, nhalf, g, tig);
        CP_WAIT0(); __syncthreads();

        // L2 (wsA); prefetch W3 -> wsB
        stage_wh_async<H>(Wg3, wsB_u);
        stage_b_async<H>(b3 + m * HID, bsB_u);
        CP_COMMIT();
        layer_fc<KC, NCW>(X, wsA, bsA, mpair, nhalf, g, tig);
        CP_WAIT0(); __syncthreads();

        // L3 (wsB); prefetch W4 -> wsA + bias4 -> bsA
        stage_w4_async<H>(Wg4, wsA_u);
        if (tid < 8) bsA[tid] = (tid < OUT_F) ? b4[m * OUT_F + tid] : 0.f;
        CP_COMMIT();
        layer_fc<KC, NCW>(X, wsB, bsB, mpair, nhalf, g, tig);
        CP_WAIT0(); __syncthreads();

        // L4 out (wsA)
        layer_out<KC>(X, wsA, bsA, out, ords, cnt, fi, e0, g, tig);
        __syncthreads();
    }
}

__global__ __launch_bounds__(NTHREADS, 1) void k_mlp_all(
    const float* __restrict__ inp,
    const float* __restrict__ W0, const float* __restrict__ b0,
    const float* __restrict__ W1, const float* __restrict__ b1,
    const float* __restrict__ W2, const float* __restrict__ b2,
    const float* __restrict__ W3, const float* __restrict__ b3,
    const float* __restrict__ W4, const float* __restrict__ b4,
    float* __restrict__ out) {
    switch (blockIdx.z) {
        case 0: mlp_body<32 >(inp, W0, b0, W1, b1, W2, b2, W3, b3, W4, b4, out); break;
        case 1: mlp_body<64 >(inp, W0, b0, W1, b1, W2, b2, W3, b3, W4, b4, out); break;
        case 2: mlp_body<96 >(inp, W0, b0, W1, b1, W2, b2, W3, b3, W4, b4, out); break;
        default: mlp_body<128>(inp, W0, b0, W1, b1, W2, b2, W3, b3, W4, b4, out); break;
    }
}

// ---------------- launch ----------------
extern "C" void kernel_launch(void* const* d_in, const int* in_sizes, int n_in,
                              void* d_out, int out_size) {
    const float* inp = (const float*)d_in[0];
    const float* W0  = (const float*)d_in[1];
    const float* b0  = (const float*)d_in[2];
    const float* W1  = (const float*)d_in[3];
    const float* b1  = (const float*)d_in[4];
    const float* W2  = (const float*)d_in[5];
    const float* b2  = (const float*)d_in[6];
    const float* W3  = (const float*)d_in[7];
    const float* b3  = (const float*)d_in[8];
    const float* W4  = (const float*)d_in[9];
    const float* b4  = (const float*)d_in[10];
    float* out = (float*)d_out;

    k_select<<<B / 256, 256>>>(inp, out);
    k_scatter<<<B / 256, 256>>>();

    size_t smem = (size_t)(MT * XP + 2 * HID * XP + 2 * HID) * sizeof(float) + MT * sizeof(int);
    cudaFuncSetAttribute(k_mlp_all, cudaFuncAttributeMaxDynamicSharedMemorySize, (int)smem);
    dim3 grid(NT_X, NM, NFACT);
    k_mlp_all<<<grid, NTHREADS, smem>>>(inp, W0, b0, W1, b1, W2, b2, W3, b3, W4, b4, out);
}

// round 14
// speedup vs baseline: 1.2603x; 1.0396x over previous
#include <cuda_runtime.h>
#include <cstdint>
#include <math.h>

// ---------------- problem constants ----------------
constexpr int B        = 16384;
constexpr int NM       = 64;
constexpr int IN_F     = 6;
constexpr int OUT_F    = 3;
constexpr int HID      = 128;
constexpr int NFACT    = 4;

constexpr int MT       = 128;   // elements per tile (MMA M)
constexpr int XP       = 132;   // smem pitch (floats)
constexpr int NTHREADS = 256;   // 8 warps = 4 m-pairs x 2 n-halves
constexpr int NSM      = 148;   // persistent grid size

constexpr int OFF_IDX  = B * NFACT * OUT_F;
constexpr int OFF_LOG  = OFF_IDX + B;
constexpr int OFF_PROB = OFF_LOG + B * NM;

#define DINL __device__ __forceinline__

// ---------------- device scratch ----------------
__device__ int g_idx[B];
__device__ int g_pcounts[64][NM];
__device__ int g_offsets[NM + 1];
__device__ int g_tprefix[NM + 1];
__device__ int g_workctr;
__device__ int g_order[B];

// ---------------- kernel 1: select + histogram + easy outputs ----------------
__global__ void k_select(const float* __restrict__ inp, float* __restrict__ out) {
    __shared__ int h[NM];
    if (threadIdx.x < NM) h[threadIdx.x] = 0;
    __syncthreads();

    int b = blockIdx.x * blockDim.x + threadIdx.x;   // 64 blocks x 256
    float x0 = inp[b * 6 + 0];
    float x2 = inp[b * 6 + 2];
    const float TPf = 6.2831853071795864769f;

    // fast path: fp32 atan2; recompute exactly only near bin boundaries
    float angf = atan2f(x2, x0);
    float vf = fmodf(angf + TPf, TPf) / TPf * 64.0f;
    float flf = floorf(vf);
    float d = vf - flf;
    int idx;
    if (d > 3e-4f && d < 1.0f - 3e-4f) {
        idx = (int)flf;
    } else {
        // reference-exact: correctly-rounded f32 atan2, then fp32 ops
        float ang = (float)atan2((double)x2, (double)x0);
        float t   = ang + TPf;
        float a   = fmodf(t, TPf);
        float v   = a / TPf * 64.0f;
        idx = (int)floorf(v);
    }
    idx = max(0, min(63, idx));

    g_idx[b] = idx;
    out[OFF_IDX + b] = (float)idx;
    atomicAdd(&h[idx], 1);

    // logits=1, probs=1/64 — coalesced grid-linear float4 writes
    float4 ones = make_float4(1.f, 1.f, 1.f, 1.f);
    float4 prob = make_float4(0.015625f, 0.015625f, 0.015625f, 0.015625f);
    float4* lg = (float4*)(out + OFF_LOG);
    float4* pb = (float4*)(out + OFF_PROB);
    size_t base = (size_t)blockIdx.x * (256 * 16) + threadIdx.x;
    #pragma unroll
    for (int i = 0; i < 16; ++i) {
        lg[base + (size_t)i * 256] = ones;
        pb[base + (size_t)i * 256] = prob;
    }

    __syncthreads();
    if (threadIdx.x < NM) g_pcounts[blockIdx.x][threadIdx.x] = h[threadIdx.x];
}

// ---------------- kernel 2: scan + scatter + work-list build ---------------
__global__ void k_scatter() {
    __shared__ int cur[NM];
    __shared__ int ws[2];
    __shared__ int ws2[2];
    int tid = threadIdx.x;

    int tot = 0, pre = 0, v = 0;
    if (tid < NM) {
        #pragma unroll 8
        for (int j = 0; j < 64; ++j) {
            int c = g_pcounts[j][tid];
            if (j < (int)blockIdx.x) pre += c;
            tot += c;
        }
        v = tot;
        #pragma unroll
        for (int d = 1; d < 32; d <<= 1) {
            int n = __shfl_up_sync(0xFFFFFFFFu, v, d);
            if ((tid & 31) >= d) v += n;
        }
        if ((tid & 31) == 31) ws[tid >> 5] = v;
    }
    // tiles-per-model scan (for work units)
    int tv = 0;
    if (tid < NM) {
        tv = (tot + MT - 1) / MT;
        #pragma unroll
        for (int d = 1; d < 32; d <<= 1) {
            int n = __shfl_up_sync(0xFFFFFFFFu, tv, d);
            if ((tid & 31) >= d) tv += n;
        }
        if ((tid & 31) == 31) ws2[tid >> 5] = tv;
    }
    __syncthreads();
    if (tid >= 32 && tid < NM) { v += ws[0]; tv += ws2[0]; }
    if (tid < NM) {
        cur[tid] = (v - tot) + pre;
        if (blockIdx.x == 0) {
            g_offsets[tid + 1] = v;
            g_tprefix[tid + 1] = tv;
            if (tid == 0) { g_offsets[0] = 0; g_tprefix[0] = 0; g_workctr = 0; }
        }
    }
    __syncthreads();

    int b = blockIdx.x * blockDim.x + tid;
    int idx = g_idx[b];
    int pos = atomicAdd(&cur[idx], 1);
    g_order[pos] = b;
}

// ---------------- tf32 / mma helpers ----------------
DINL uint32_t tf32u(float x) {
    uint32_t r;
    asm("cvt.rna.tf32.f32 %0, %1;" : "=r"(r) : "f"(x));
    return r;
}
DINL float tf32f(float x) { return __uint_as_float(tf32u(x)); }

DINL void mma8(float& c0, float& c1, float& c2, float& c3,
               uint32_t a0, uint32_t a1, uint32_t a2, uint32_t a3,
               uint32_t b0, uint32_t b1) {
    asm volatile(
        "mma.sync.aligned.m16n8k8.row.col.f32.tf32.tf32.f32 "
        "{%0,%1,%2,%3}, {%4,%5,%6,%7}, {%8,%9}, {%0,%1,%2,%3};"
        : "+f"(c0), "+f"(c1), "+f"(c2), "+f"(c3)
        : "r"(a0), "r"(a1), "r"(a2), "r"(a3), "r"(b0), "r"(b1));
}

DINL uint32_t smem_u32(const void* p) {
    uint32_t a;
    asm("{ .reg .u64 t; cvta.to.shared.u64 t, %1; cvt.u32.u64 %0, t; }" : "=r"(a) : "l"(p));
    return a;
}
DINL void cpa16(uint32_t dst, const float* src) {
    asm volatile("cp.async.cg.shared.global [%0], [%1], 16;" :: "r"(dst), "l"(src));
}
#define CP_COMMIT() asm volatile("cp.async.commit_group;" ::: "memory")
#define CP_WAIT0()  asm volatile("cp.async.wait_group 0;" ::: "memory")
#define BAR_PAIR(id) asm volatile("bar.sync %0, 64;" :: "r"(id) : "memory")

// ---------------- async staging (raw fp32, row-major [n][k], pitch XP) ------
template<int H>
DINL void stage_wh_async(const float* __restrict__ Wg, uint32_t dst_u) {
    constexpr int J = H / 4;
    for (int i = threadIdx.x; i < H * J; i += NTHREADS) {
        int n = i / J, j = i - n * J;
        cpa16(dst_u + (uint32_t)(n * XP + 4 * j) * 4, Wg + n * HID + 4 * j);
    }
}
template<int H>
DINL void stage_w4_async(const float* __restrict__ Wg, uint32_t dst_u) {
    constexpr int J = H / 4;
    for (int i = threadIdx.x; i < OUT_F * J; i += NTHREADS) {
        int o = i / J, j = i - o * J;
        cpa16(dst_u + (uint32_t)(o * XP + 4 * j) * 4, Wg + o * HID + 4 * j);
    }
}
template<int H>
DINL void stage_b_async(const float* __restrict__ bg, uint32_t dst_u) {
    if (threadIdx.x < H / 4) cpa16(dst_u + threadIdx.x * 16, bg + 4 * threadIdx.x);
}
template<int H>
DINL void stage_w0(const float* __restrict__ Wg, float* __restrict__ Ws) {
    for (int n = threadIdx.x; n < H; n += NTHREADS) {
        const float* src = Wg + n * IN_F;
        float* dst = Ws + n * XP;
        dst[0] = src[0]; dst[1] = src[1]; dst[2] = src[2];
        dst[3] = src[3]; dst[4] = src[4]; dst[5] = src[5];
        dst[6] = 0.f; dst[7] = 0.f;
    }
}

// ---------------- fused FC layer: M-block2, two-phase K, pair barriers ------
template<int KC, int NCW>
DINL void layer_fc(float* __restrict__ X, const float* __restrict__ Ws,
                   const float* __restrict__ Bs,
                   int mpair, int nhalf, int g, int tig) {
    const int r0 = mpair * 32;
    constexpr int NPH = (KC > 1) ? 2 : 1;
    constexpr int KH  = KC / NPH;

    float c[2][NCW][4];
    #pragma unroll
    for (int nc = 0; nc < NCW; ++nc) {
        float2 bi = *(const float2*)(Bs + (nhalf * NCW + nc) * 8 + 2 * tig);
        #pragma unroll
        for (int mt = 0; mt < 2; ++mt) {
            c[mt][nc][0] = bi.x; c[mt][nc][1] = bi.y;
            c[mt][nc][2] = bi.x; c[mt][nc][3] = bi.y;
        }
    }

    #pragma unroll
    for (int ph = 0; ph < NPH; ++ph) {
        uint32_t a[2][KH][4];
        #pragma unroll
        for (int mt = 0; mt < 2; ++mt) {
            #pragma unroll
            for (int j = 0; j < KH; ++j) {
                const float* xr = X + (r0 + mt * 16 + g) * XP + (ph * KH + j) * 8 + tig;
                a[mt][j][0] = __float_as_uint(xr[0]);
                a[mt][j][2] = __float_as_uint(xr[4]);
                a[mt][j][1] = __float_as_uint(xr[8 * XP]);
                a[mt][j][3] = __float_as_uint(xr[8 * XP + 4]);
            }
        }
        #pragma unroll
        for (int nc = 0; nc < NCW; ++nc) {
            const int row = (nhalf * NCW + nc) * 8 + g;
            #pragma unroll
            for (int j = 0; j < KH; ++j) {
                const float* w = Ws + row * XP + (ph * KH + j) * 8 + tig;
                uint32_t b0 = __float_as_uint(w[0]);
                uint32_t b1 = __float_as_uint(w[4]);
                mma8(c[0][nc][0], c[0][nc][1], c[0][nc][2], c[0][nc][3],
                     a[0][j][0], a[0][j][1], a[0][j][2], a[0][j][3], b0, b1);
                mma8(c[1][nc][0], c[1][nc][1], c[1][nc][2], c[1][nc][3],
                     a[1][j][0], a[1][j][1], a[1][j][2], a[1][j][3], b0, b1);
            }
        }
    }

    BAR_PAIR(1 + mpair);   // pair-local: A reads done before partner stores

    #pragma unroll
    for (int mt = 0; mt < 2; ++mt) {
        #pragma unroll
        for (int nc = 0; nc < NCW; ++nc) {
            const int n0 = (nhalf * NCW + nc) * 8;
            float2 v;
            v.x = tf32f(fmaxf(c[mt][nc][0], 0.f));
            v.y = tf32f(fmaxf(c[mt][nc][1], 0.f));
            *(float2*)(X + (r0 + mt * 16 + g) * XP + n0 + 2 * tig) = v;
            v.x = tf32f(fmaxf(c[mt][nc][2], 0.f));
            v.y = tf32f(fmaxf(c[mt][nc][3], 0.f));
            *(float2*)(X + (r0 + mt * 16 + 8 + g) * XP + n0 + 2 * tig) = v;
        }
    }
}

// output layer: 8 warps x 16 rows, N=8 (3 valid)
template<int KC>
DINL void layer_out(const float* __restrict__ X, const float* __restrict__ Ws,
                    const float* __restrict__ Bs, float* __restrict__ out,
                    const int* __restrict__ ords, int cnt, int fi,
                    int e0, int g, int tig) {
    uint32_t a[KC][4];
    #pragma unroll
    for (int kc = 0; kc < KC; ++kc) {
        const float* xr = X + (e0 + g) * XP + kc * 8 + tig;
        a[kc][0] = __float_as_uint(xr[0]);
        a[kc][2] = __float_as_uint(xr[4]);
        a[kc][1] = __float_as_uint(xr[8 * XP]);
        a[kc][3] = __float_as_uint(xr[8 * XP + 4]);
    }
    float c0 = Bs[2 * tig], c1 = Bs[2 * tig + 1];
    float c2 = c0, c3 = c1;
    #pragma unroll
    for (int kc = 0; kc < KC; ++kc) {
        const float* w = Ws + g * XP + kc * 8 + tig;
        mma8(c0, c1, c2, c3, a[kc][0], a[kc][1], a[kc][2], a[kc][3],
             __float_as_uint(w[0]), __float_as_uint(w[4]));
    }
    const int col0 = 2 * tig, col1 = 2 * tig + 1;
    const int e1 = e0 + g, e2 = e0 + 8 + g;
    if (e1 < cnt) {
        const int base = ords[e1] * (NFACT * OUT_F) + fi * OUT_F;
        if (col0 < OUT_F) out[base + col0] = c0;
        if (col1 < OUT_F) out[base + col1] = c1;
    }
    if (e2 < cnt) {
        const int base = ords[e2] * (NFACT * OUT_F) + fi * OUT_F;
        if (col0 < OUT_F) out[base + col0] = c2;
        if (col1 < OUT_F) out[base + col1] = c3;
    }
}

// ---------------- one tile (model m, factor fi, element range) --------------
template<int H>
DINL void tile_body(const float* __restrict__ inp,
                    const float* __restrict__ W0, const float* __restrict__ b0,
                    const float* __restrict__ W1, const float* __restrict__ b1,
                    const float* __restrict__ W2, const float* __restrict__ b2,
                    const float* __restrict__ W3, const float* __restrict__ b3,
                    const float* __restrict__ W4, const float* __restrict__ b4,
                    float* __restrict__ out,
                    float* X, float* wsA, float* wsB, float* bsA, float* bsB,
                    int* ords, uint32_t wsA_u, uint32_t wsB_u,
                    uint32_t bsA_u, uint32_t bsB_u,
                    int m, int beg, int cnt) {
    constexpr int KC  = H / 8;
    constexpr int NCW = H / 16;
    constexpr int fi  = H / 32 - 1;

    const int tid = threadIdx.x;
    const int wid = tid >> 5;
    const int lane = tid & 31;
    const int g = lane >> 2, tig = lane & 3;
    const int mpair = wid >> 1, nhalf = wid & 1;
    const int e0 = wid * 16;

    const float* Wg0 = W0 + m * (HID * IN_F);
    const float* Wg1 = W1 + m * (HID * HID);
    const float* Wg2 = W2 + m * (HID * HID);
    const float* Wg3 = W3 + m * (HID * HID);
    const float* Wg4 = W4 + m * (OUT_F * HID);

    for (int i = tid; i < MT; i += NTHREADS)
        ords[i] = (i < cnt) ? g_order[beg + i] : 0;
    __syncthreads();

    for (int i = tid; i < MT * 8; i += NTHREADS) {
        int e = i >> 3, c = i & 7;
        X[e * XP + c] = (c < IN_F) ? tf32f(inp[(size_t)ords[e] * IN_F + c]) : 0.f;
    }
    stage_w0<H>(Wg0, wsA);
    for (int i = tid; i < H; i += NTHREADS) bsA[i] = b0[m * HID + i];
    __syncthreads();

    stage_wh_async<H>(Wg1, wsB_u);
    stage_b_async<H>(b1 + m * HID, bsB_u);
    CP_COMMIT();
    layer_fc<1, NCW>(X, wsA, bsA, mpair, nhalf, g, tig);
    CP_WAIT0(); __syncthreads();

    stage_wh_async<H>(Wg2, wsA_u);
    stage_b_async<H>(b2 + m * HID, bsA_u);
    CP_COMMIT();
    layer_fc<KC, NCW>(X, wsB, bsB, mpair, nhalf, g, tig);
    CP_WAIT0(); __syncthreads();

    stage_wh_async<H>(Wg3, wsB_u);
    stage_b_async<H>(b3 + m * HID, bsB_u);
    CP_COMMIT();
    layer_fc<KC, NCW>(X, wsA, bsA, mpair, nhalf, g, tig);
    CP_WAIT0(); __syncthreads();

    stage_w4_async<H>(Wg4, wsA_u);
    if (tid < 8) bsA[tid] = (tid < OUT_F) ? b4[m * OUT_F + tid] : 0.f;
    CP_COMMIT();
    layer_fc<KC, NCW>(X, wsB, bsB, mpair, nhalf, g, tig);
    CP_WAIT0(); __syncthreads();

    layer_out<KC>(X, wsA, bsA, out, ords, cnt, fi, e0, g, tig);
    __syncthreads();
}

// ---------------- persistent MLP kernel with work stealing ------------------
__global__ __launch_bounds__(NTHREADS, 1) void k_mlp_all(
    const float* __restrict__ inp,
    const float* __restrict__ W0, const float* __restrict__ b0,
    const float* __restrict__ W1, const float* __restrict__ b1,
    const float* __restrict__ W2, const float* __restrict__ b2,
    const float* __restrict__ W3, const float* __restrict__ b3,
    const float* __restrict__ W4, const float* __restrict__ b4,
    float* __restrict__ out) {
    extern __shared__ float sm[];
    float* X   = sm;                     // MT*XP
    float* wsA = X + MT * XP;            // HID*XP
    float* wsB = wsA + HID * XP;         // HID*XP
    float* bsA = wsB + HID * XP;         // HID
    float* bsB = bsA + HID;              // HID
    int*  ords = (int*)(bsB + HID);      // MT
    const uint32_t wsA_u = smem_u32(wsA);
    const uint32_t wsB_u = smem_u32(wsB);
    const uint32_t bsA_u = smem_u32(bsA);
    const uint32_t bsB_u = smem_u32(bsB);

    __shared__ int tprefix[NM + 1];
    __shared__ int s_unit;
    const int tid = threadIdx.x;
    if (tid <= NM) tprefix[tid] = g_tprefix[tid];
    __syncthreads();
    const int NU = NFACT * tprefix[NM];

    for (;;) {
        if (tid == 0) s_unit = atomicAdd(&g_workctr, 1);
        __syncthreads();
        const int u = s_unit;
        if (u >= NU) break;

        const int f = u & 3;
        const int r = u >> 2;
        // binary search: largest m with tprefix[m] <= r
        int lo = 0, hi = NM;
        while (hi - lo > 1) {
            int mid = (lo + hi) >> 1;
            if (tprefix[mid] <= r) lo = mid; else hi = mid;
        }
        const int m = lo;
        const int t = r - tprefix[m];
        const int off0 = g_offsets[m];
        const int tot = g_offsets[m + 1] - off0;
        const int beg = off0 + t * MT;
        const int cnt = min(MT, tot - t * MT);

        switch (f) {
            case 0: tile_body<32 >(inp, W0, b0, W1, b1, W2, b2, W3, b3, W4, b4, out,
                                   X, wsA, wsB, bsA, bsB, ords,
                                   wsA_u, wsB_u, bsA_u, bsB_u, m, beg, cnt); break;
            case 1: tile_body<64 >(inp, W0, b0, W1, b1, W2, b2, W3, b3, W4, b4, out,
                                   X, wsA, wsB, bsA, bsB, ords,
                                   wsA_u, wsB_u, bsA_u, bsB_u, m, beg, cnt); break;
            case 2: tile_body<96 >(inp, W0, b0, W1, b1, W2, b2, W3, b3, W4, b4, out,
                                   X, wsA, wsB, bsA, bsB, ords,
                                   wsA_u, wsB_u, bsA_u, bsB_u, m, beg, cnt); break;
            default: tile_body<128>(inp, W0, b0, W1, b1, W2, b2, W3, b3, W4, b4, out,
                                    X, wsA, wsB, bsA, bsB, ords,
                                    wsA_u, wsB_u, bsA_u, bsB_u, m, beg, cnt); break;
        }
        // tile_body ends with __syncthreads -> safe to rewrite s_unit next iter
    }
}

// ---------------- launch ----------------
extern "C" void kernel_launch(void* const* d_in, const int* in_sizes, int n_in,
                              void* d_out, int out_size) {
    const float* inp = (const float*)d_in[0];
    const float* W0  = (const float*)d_in[1];
    const float* b0  = (const float*)d_in[2];
    const float* W1  = (const float*)d_in[3];
    const float* b1  = (const float*)d_in[4];
    const float* W2  = (const float*)d_in[5];
    const float* b2  = (const float*)d_in[6];
    const float* W3  = (const float*)d_in[7];
    const float* b3  = (const float*)d_in[8];
    const float* W4  = (const float*)d_in[9];
    const float* b4  = (const float*)d_in[10];
    float* out = (float*)d_out;

    k_select<<<B / 256, 256>>>(inp, out);
    k_scatter<<<B / 256, 256>>>();

    size_t smem = (size_t)(MT * XP + 2 * HID * XP + 2 * HID) * sizeof(float) + MT * sizeof(int);
    cudaFuncSetAttribute(k_mlp_all, cudaFuncAttributeMaxDynamicSharedMemorySize, (int)smem);
    k_mlp_all<<<NSM, NTHREADS, smem>>>(inp, W0, b0, W1, b1, W2, b2, W3, b3, W4, b4, out);
}